// round 1
// baseline (speedup 1.0000x reference)
#include <cuda_runtime.h>
#include <cstdint>

// Problem constants (fixed by setup_inputs)
#define HH   300
#define G4   1200          // 4*H
#define KK   600           // 2*H (x | h concatenated)
#define BCH  8             // batch rows per CTA
#define NT   256           // threads per CTA

// Persistent scratch (allocation-free rule: __device__ globals)
__device__ float Wt_g[KK * G4];      // [k][n]  k-major concat of W_ih|W_hh, 2.88 MB
__device__ float WoutT_g[HH * HH];   // [k][n]  W_out transposed, 360 KB
__device__ float bias_g[G4];         // b_ih + b_hh

// ---------------- packed f32x2 helpers (Blackwell-only PTX) ----------------
__device__ __forceinline__ unsigned long long pack2(float x, float y) {
    unsigned long long r;
    asm("mov.b64 %0, {%1, %2};" : "=l"(r) : "f"(x), "f"(y));
    return r;
}
__device__ __forceinline__ void ffma2(unsigned long long& d,
                                      unsigned long long a,
                                      unsigned long long b) {
    asm("fma.rn.f32x2 %0, %1, %2, %0;" : "+l"(d) : "l"(a), "l"(b));
}
__device__ __forceinline__ float2 unpack2(unsigned long long v) {
    float2 r;
    asm("mov.b64 {%0, %1}, %2;" : "=f"(r.x), "=f"(r.y) : "l"(v));
    return r;
}
__device__ __forceinline__ float sigmoidf(float x) {
    return 1.0f / (1.0f + __expf(-x));
}

// ---------------- prep: transpose weights to k-major, fuse biases ----------------
__global__ void prep_kernel(const float* __restrict__ W_ih,
                            const float* __restrict__ W_hh,
                            const float* __restrict__ b_ih,
                            const float* __restrict__ b_hh,
                            const float* __restrict__ W_out) {
    int idx = blockIdx.x * blockDim.x + threadIdx.x;
    if (idx < KK * G4) {
        int k = idx / G4;
        int n = idx % G4;
        Wt_g[idx] = (k < HH) ? W_ih[n * HH + k] : W_hh[n * HH + (k - HH)];
    }
    int i2 = idx - KK * G4;
    if (i2 >= 0 && i2 < HH * HH) {
        int k = i2 / HH;
        int n = i2 % HH;
        WoutT_g[i2] = W_out[n * HH + k];
    }
    int i3 = idx - (KK * G4 + HH * HH);
    if (i3 >= 0 && i3 < G4) {
        bias_g[i3] = b_ih[i3] + b_hh[i3];
    }
}

// ---------------- main persistent LSTM kernel ----------------
// SMEM layout (floats):
//   xh [KK][8]   = 4800   (x rows 0..299, h rows 300..599; pairs (b0,b1) adjacent)
//   cs [HH][8]   = 2400
//   hn [HH][8]   = 2400
//   gs [G4][8]   = 9600
// total 19200 floats = 76.8 KB dynamic SMEM
__global__ void __launch_bounds__(NT, 1)
lstm_main(const float* __restrict__ h0,
          const float* __restrict__ c0,
          const float* __restrict__ start,
          const float* __restrict__ b_out,
          float* __restrict__ out,
          int B, int steps) {
    extern __shared__ float sm[];
    float* xh = sm;
    float* cs = xh + KK * BCH;
    float* hn = cs + HH * BCH;
    float* gs = hn + HH * BCH;

    const int tid = threadIdx.x;
    const int r0 = blockIdx.x * BCH;

    // load initial state: x = start, h = h0, c = c0 (layout [k][b])
    for (int idx = tid; idx < HH * BCH; idx += NT) {
        int k = idx >> 3;
        int b = idx & 7;
        xh[k * BCH + b]        = start[(size_t)(r0 + b) * HH + k];
        xh[(HH + k) * BCH + b] = h0[(size_t)(r0 + b) * HH + k];
        cs[idx]                = c0[(size_t)(r0 + b) * HH + k];
    }
    __syncthreads();

    const unsigned long long* xh2 = (const unsigned long long*)xh;
    const unsigned long long* hn2 = (const unsigned long long*)hn;
    unsigned long long* gs2 = (unsigned long long*)gs;

    const bool has5 = (tid + 4 * NT) < G4;   // fifth gate column valid?
    const bool hasO2 = (tid + NT) < HH;      // second out column valid?

    for (int t = 0; t < steps; ++t) {
        // ================= gates GEMM: gs[n][b] = bias[n] + sum_k xh[k][b]*Wt[k][n]
        unsigned long long acc[5][4];
        #pragma unroll
        for (int j = 0; j < 5; ++j) {
            int n = tid + j * NT;
            if (n >= G4) n = G4 - 1;
            float bv = bias_g[n];
            unsigned long long bb = pack2(bv, bv);
            #pragma unroll
            for (int p = 0; p < 4; ++p) acc[j][p] = bb;
        }
        #pragma unroll 2
        for (int k = 0; k < KK; ++k) {
            unsigned long long xp0 = xh2[k * 4 + 0];
            unsigned long long xp1 = xh2[k * 4 + 1];
            unsigned long long xp2 = xh2[k * 4 + 2];
            unsigned long long xp3 = xh2[k * 4 + 3];
            const float* wrow = &Wt_g[(size_t)k * G4];
            #pragma unroll
            for (int j = 0; j < 5; ++j) {
                int n = tid + j * NT;
                if (n >= G4) n = G4 - 1;          // clamped duplicate work, no store
                float w = __ldg(&wrow[n]);
                unsigned long long w2 = pack2(w, w);
                ffma2(acc[j][0], xp0, w2);
                ffma2(acc[j][1], xp1, w2);
                ffma2(acc[j][2], xp2, w2);
                ffma2(acc[j][3], xp3, w2);
            }
        }
        #pragma unroll
        for (int j = 0; j < 5; ++j) {
            int n = tid + j * NT;
            if (j < 4 || has5) {
                #pragma unroll
                for (int p = 0; p < 4; ++p) gs2[n * 4 + p] = acc[j][p];
            }
        }
        __syncthreads();

        // ================= elementwise LSTM update
        for (int m = tid; m < HH; m += NT) {
            #pragma unroll
            for (int b = 0; b < BCH; ++b) {
                float ig = sigmoidf(gs[m * BCH + b]);
                float fg = sigmoidf(gs[(HH + m) * BCH + b]);
                float gg = tanhf(gs[(2 * HH + m) * BCH + b]);
                float og = sigmoidf(gs[(3 * HH + m) * BCH + b]);
                float c  = fg * cs[m * BCH + b] + ig * gg;
                cs[m * BCH + b] = c;
                float h  = og * tanhf(c);
                hn[m * BCH + b] = h;
                xh[(HH + m) * BCH + b] = h;   // h part of next-step input
            }
        }
        __syncthreads();

        // ================= out GEMM: out[b][n] = b_out[n] + sum_k hn[k][b]*WoutT[k][n]
        unsigned long long oacc[2][4];
        #pragma unroll
        for (int j = 0; j < 2; ++j) {
            int n = tid + j * NT;
            if (n >= HH) n = HH - 1;
            float bv = __ldg(&b_out[n]);
            unsigned long long bb = pack2(bv, bv);
            #pragma unroll
            for (int p = 0; p < 4; ++p) oacc[j][p] = bb;
        }
        #pragma unroll 2
        for (int k = 0; k < HH; ++k) {
            unsigned long long hp0 = hn2[k * 4 + 0];
            unsigned long long hp1 = hn2[k * 4 + 1];
            unsigned long long hp2 = hn2[k * 4 + 2];
            unsigned long long hp3 = hn2[k * 4 + 3];
            const float* wrow = &WoutT_g[(size_t)k * HH];
            #pragma unroll
            for (int j = 0; j < 2; ++j) {
                int n = tid + j * NT;
                if (n >= HH) n = HH - 1;
                float w = __ldg(&wrow[n]);
                unsigned long long w2 = pack2(w, w);
                ffma2(oacc[j][0], hp0, w2);
                ffma2(oacc[j][1], hp1, w2);
                ffma2(oacc[j][2], hp2, w2);
                ffma2(oacc[j][3], hp3, w2);
            }
        }
        float* orow = out + (size_t)t * B * HH;
        #pragma unroll
        for (int j = 0; j < 2; ++j) {
            int n = tid + j * NT;
            if (j == 0 || hasO2) {
                #pragma unroll
                for (int p = 0; p < 4; ++p) {
                    float2 v = unpack2(oacc[j][p]);
                    orow[(size_t)(r0 + 2 * p) * HH + n]     = v.x;
                    orow[(size_t)(r0 + 2 * p + 1) * HH + n] = v.y;
                    xh[n * BCH + 2 * p]     = v.x;     // x part of next-step input
                    xh[n * BCH + 2 * p + 1] = v.y;
                }
            }
        }
        __syncthreads();
    }
}

// ---------------- launch ----------------
extern "C" void kernel_launch(void* const* d_in, const int* in_sizes, int n_in,
                              void* d_out, int out_size) {
    const float* h0    = (const float*)d_in[0];
    const float* c0    = (const float*)d_in[1];
    const float* start = (const float*)d_in[2];
    const float* W_ih  = (const float*)d_in[3];
    const float* W_hh  = (const float*)d_in[4];
    const float* b_ih  = (const float*)d_in[5];
    const float* b_hh  = (const float*)d_in[6];
    const float* W_out = (const float*)d_in[7];
    const float* b_out = (const float*)d_in[8];

    int B = in_sizes[0] / HH;                  // 1024
    int steps = out_size / (B * HH);           // 256 (robust: derived from out_size)

    // prep: transpose weights + fuse biases (cheap; part of the capture)
    int prep_elems = KK * G4 + HH * HH + G4;
    prep_kernel<<<(prep_elems + 255) / 256, 256>>>(W_ih, W_hh, b_ih, b_hh, W_out);

    size_t smem_bytes = (size_t)(KK * BCH + HH * BCH + HH * BCH + G4 * BCH) * sizeof(float);
    static bool attr_set = false;   // idempotent attribute, not state that changes behavior
    cudaFuncSetAttribute(lstm_main, cudaFuncAttributeMaxDynamicSharedMemorySize,
                         (int)smem_bytes);
    (void)attr_set;

    lstm_main<<<B / BCH, NT, smem_bytes>>>(h0, c0, start, b_out,
                                           (float*)d_out, B, steps);
}

// round 2
// speedup vs baseline: 1.9640x; 1.9640x over previous
#include <cuda_runtime.h>
#include <cstdint>

// Problem constants
#define HH   300
#define G4   1200          // 4*H
#define KK   600           // 2*H (x | h)
#define BCH  8             // batch rows per CTA
#define NT   320           // threads per CTA (300 compute + producer lanes)
#define CHUNK_BYTES 48000  // 10 gates k-rows (1200 f32) or 40 out k-rows (300 f32)
#define NCHUNK 4
#define GT 60              // gates tiles per step (600 k / 10)
#define OT 8               // out tiles per step (300 k: 7x40 + 1x20)
#define TPS (GT + OT)      // 68 tiles per step

// SMEM layout (bytes)
#define SM_XH    0                      // 600*8 floats = 19200 B
#define SM_BAR   19200                  // 4 slots x (full u64 + empty u64) = 64 B
#define SM_CHUNK 19264                  // 4 x 48000 = 192000 B
#define SM_TOTAL (SM_CHUNK + NCHUNK*CHUNK_BYTES)   // 211264 B

// Persistent weights (allocation-free rule: __device__ globals)
__device__ __align__(256) float Wt2_g[KK * G4];    // [k][m*4+g] gate-interleaved
__device__ __align__(256) float WoutT_g[HH * HH];  // [k][n]
__device__ __align__(256) float bias2_g[G4];       // [m*4+g] fused b_ih+b_hh

// ---------------- packed f32x2 helpers ----------------
__device__ __forceinline__ unsigned long long pack2(float x, float y) {
    unsigned long long r;
    asm("mov.b64 %0, {%1, %2};" : "=l"(r) : "f"(x), "f"(y));
    return r;
}
__device__ __forceinline__ void ffma2(unsigned long long& d,
                                      unsigned long long a,
                                      unsigned long long b) {
    asm("fma.rn.f32x2 %0, %1, %2, %0;" : "+l"(d) : "l"(a), "l"(b));
}
__device__ __forceinline__ float2 unpack2(unsigned long long v) {
    float2 r;
    asm("mov.b64 {%0, %1}, %2;" : "=f"(r.x), "=f"(r.y) : "l"(v));
    return r;
}
__device__ __forceinline__ float sigf(float x) {
    return __fdividef(1.0f, 1.0f + __expf(-x));
}
__device__ __forceinline__ float tanhf_fast(float x) {
    return 1.0f - 2.0f * __fdividef(1.0f, __expf(2.0f * x) + 1.0f);
}

// ---------------- mbarrier / bulk-copy PTX ----------------
__device__ __forceinline__ uint32_t smem_u32(const void* p) {
    uint32_t a;
    asm("{ .reg .u64 t; cvta.to.shared.u64 t, %1; cvt.u32.u64 %0, t; }"
        : "=r"(a) : "l"(p));
    return a;
}
__device__ __forceinline__ uint32_t ctarank() {
    uint32_t r; asm("mov.u32 %0, %%cluster_ctarank;" : "=r"(r)); return r;
}
__device__ __forceinline__ void mbar_init(uint32_t a, uint32_t cnt) {
    asm volatile("mbarrier.init.shared.b64 [%0], %1;" :: "r"(a), "r"(cnt) : "memory");
}
__device__ __forceinline__ void mbar_expect_tx(uint32_t a, uint32_t bytes) {
    asm volatile("mbarrier.arrive.expect_tx.shared.b64 _, [%0], %1;"
                 :: "r"(a), "r"(bytes) : "memory");
}
__device__ __forceinline__ void mbar_arrive(uint32_t a) {
    asm volatile("mbarrier.arrive.shared.b64 _, [%0];" :: "r"(a) : "memory");
}
__device__ __forceinline__ void mbar_arrive_cluster(uint32_t a, uint32_t rankTgt) {
    asm volatile(
        "{\n\t.reg .b32 r;\n\t"
        "mapa.shared::cluster.u32 r, %0, %1;\n\t"
        "mbarrier.arrive.shared::cluster.b64 _, [r];\n\t}"
        :: "r"(a), "r"(rankTgt) : "memory");
}
__device__ __forceinline__ void mbar_wait_acq(uint32_t a, uint32_t parity) {
    asm volatile(
        "{\n\t.reg .pred P;\n"
        "LW_%=:\n\t"
        "mbarrier.try_wait.parity.acquire.cta.shared::cta.b64 P, [%0], %1, 0x989680;\n\t"
        "@P bra.uni LD_%=;\n\t"
        "bra.uni LW_%=;\n"
        "LD_%=:\n\t}"
        :: "r"(a), "r"(parity) : "memory");
}
__device__ __forceinline__ void mbar_wait_rlx(uint32_t a, uint32_t parity) {
    asm volatile(
        "{\n\t.reg .pred P;\n"
        "LW_%=:\n\t"
        "mbarrier.try_wait.parity.relaxed.cta.shared::cta.b64 P, [%0], %1, 0x989680;\n\t"
        "@P bra.uni LD_%=;\n\t"
        "bra.uni LW_%=;\n"
        "LD_%=:\n\t}"
        :: "r"(a), "r"(parity) : "memory");
}
// bulk copy global->shared, multicast to cluster mask, complete_tx on mbar
__device__ __forceinline__ void bulk_mc(uint32_t dst, const void* src,
                                        uint32_t bytes, uint32_t mbar,
                                        uint16_t mask) {
    asm volatile(
        "cp.async.bulk.shared::cluster.global.mbarrier::complete_tx::bytes"
        ".multicast::cluster [%0], [%1], %2, [%3], %4;"
        :: "r"(dst), "l"(src), "r"(bytes), "r"(mbar), "h"(mask) : "memory");
}

// ---------------- prep: interleave/transposed weights, fused bias ----------------
__global__ void prep_kernel(const float* __restrict__ W_ih,
                            const float* __restrict__ W_hh,
                            const float* __restrict__ b_ih,
                            const float* __restrict__ b_hh,
                            const float* __restrict__ W_out) {
    int idx = blockIdx.x * blockDim.x + threadIdx.x;
    if (idx < KK * G4) {
        int k = idx / G4;
        int col = idx % G4;            // m*4+g
        int m = col >> 2, g = col & 3;
        int n = m + HH * g;
        Wt2_g[idx] = (k < HH) ? W_ih[n * HH + k] : W_hh[n * HH + (k - HH)];
    }
    int i2 = idx - KK * G4;
    if (i2 >= 0 && i2 < HH * HH) {
        int k = i2 / HH, n = i2 % HH;
        WoutT_g[i2] = W_out[n * HH + k];
    }
    int i3 = idx - (KK * G4 + HH * HH);
    if (i3 >= 0 && i3 < G4) {
        int m = i3 >> 2, g = i3 & 3;
        bias2_g[i3] = b_ih[m + HH * g] + b_hh[m + HH * g];
    }
}

// ---------------- main persistent LSTM kernel ----------------
__global__ void __launch_bounds__(NT, 1) __cluster_dims__(2, 1, 1)
lstm_main(const float* __restrict__ h0,
          const float* __restrict__ c0,
          const float* __restrict__ start,
          const float* __restrict__ b_out,
          float* __restrict__ out,
          int B, int steps) {
    extern __shared__ char smem[];
    float* xh = (float*)(smem + SM_XH);
    unsigned long long* xh2 = (unsigned long long*)xh;
    const ulonglong2* xh4 = (const ulonglong2*)xh;

    const uint32_t sbase = smem_u32(smem);
    const uint32_t bar0 = sbase + SM_BAR;
    const int tid = threadIdx.x;
    const int m = tid;                      // compute column (valid when < 300)
    const uint32_t rank = ctarank();
    const uint32_t peer = rank ^ 1u;
    const int r0 = blockIdx.x * BCH;
    const int TOTAL = steps * TPS;

    // barriers: full[s] = bar0 + s*16 ; empty[s] = bar0 + s*16 + 8
    if (tid == 0) {
        #pragma unroll
        for (int s = 0; s < NCHUNK; ++s) {
            mbar_init(bar0 + s * 16, 1);           // full: 1 expect_tx arrive
            mbar_init(bar0 + s * 16 + 8, 2 * NT);  // empty: both CTAs' threads
        }
    }
    __syncthreads();
    asm volatile("barrier.cluster.arrive.aligned;" ::: "memory");
    asm volatile("barrier.cluster.wait.aligned;" ::: "memory");

    // initial state: x = start, h = h0 into xh; c into registers
    for (int idx = tid; idx < HH * BCH; idx += NT) {
        int k = idx >> 3, b = idx & 7;
        xh[k * BCH + b]        = start[(size_t)(r0 + b) * HH + k];
        xh[(HH + k) * BCH + b] = h0[(size_t)(r0 + b) * HH + k];
    }
    float cst[BCH];
    unsigned long long pb[4], pbo = 0;
    if (m < HH) {
        #pragma unroll
        for (int b = 0; b < BCH; ++b) cst[b] = c0[(size_t)(r0 + b) * HH + m];
        float4 bb = *(const float4*)&bias2_g[m * 4];
        pb[0] = pack2(bb.x, bb.x); pb[1] = pack2(bb.y, bb.y);
        pb[2] = pack2(bb.z, bb.z); pb[3] = pack2(bb.w, bb.w);
        float bo = __ldg(&b_out[m]);
        pbo = pack2(bo, bo);
    }
    __syncthreads();

    // producer cursor (only meaningful in thread 300)
    int p_slot = 0, p_phase = 1;
    auto produce = [&](int gi) {
        mbar_wait_rlx(bar0 + p_slot * 16 + 8, (uint32_t)p_phase);  // wait empty
        int j = gi % TPS;
        const char* src; int bytes;
        if (j < GT) {
            src = (const char*)Wt2_g + (size_t)j * CHUNK_BYTES;
            bytes = CHUNK_BYTES;
        } else {
            int jj = j - GT;
            src = (const char*)WoutT_g + (size_t)jj * CHUNK_BYTES;
            bytes = (jj < OT - 1) ? CHUNK_BYTES : 24000;
        }
        int half = bytes >> 1;
        uint32_t full = bar0 + p_slot * 16;
        uint32_t dst = sbase + SM_CHUNK + p_slot * CHUNK_BYTES + rank * half;
        mbar_expect_tx(full, (uint32_t)bytes);     // expect FULL tile locally
        bulk_mc(dst, src + (size_t)rank * half, (uint32_t)half, full, 0x3);
        if (++p_slot == NCHUNK) { p_slot = 0; p_phase ^= 1; }
    };

    if (tid == 300) {
        #pragma unroll
        for (int i = 0; i < NCHUNK; ++i) produce(i);
    }

    int c_slot = 0, c_phase = 0, gi = 0;

    for (int t = 0; t < steps; ++t) {
        // =========== gates GEMM: acc[g] pairs over batch ===========
        unsigned long long acc[4][4];
        if (m < HH) {
            #pragma unroll
            for (int g = 0; g < 4; ++g)
                #pragma unroll
                for (int p = 0; p < 4; ++p) acc[g][p] = pb[g];
        }
        for (int tile = 0; tile < GT; ++tile) {
            mbar_wait_acq(bar0 + c_slot * 16, (uint32_t)c_phase);
            const char* cbase = smem + SM_CHUNK + c_slot * CHUNK_BYTES;
            if (m < HH) {
                #pragma unroll
                for (int kl = 0; kl < 10; ++kl) {
                    int k = tile * 10 + kl;
                    ulonglong2 xa = xh4[k * 2];
                    ulonglong2 xb = xh4[k * 2 + 1];
                    float4 w = *(const float4*)(cbase + kl * 4800 + m * 16);
                    unsigned long long wp;
                    wp = pack2(w.x, w.x);
                    ffma2(acc[0][0], xa.x, wp); ffma2(acc[0][1], xa.y, wp);
                    ffma2(acc[0][2], xb.x, wp); ffma2(acc[0][3], xb.y, wp);
                    wp = pack2(w.y, w.y);
                    ffma2(acc[1][0], xa.x, wp); ffma2(acc[1][1], xa.y, wp);
                    ffma2(acc[1][2], xb.x, wp); ffma2(acc[1][3], xb.y, wp);
                    wp = pack2(w.z, w.z);
                    ffma2(acc[2][0], xa.x, wp); ffma2(acc[2][1], xa.y, wp);
                    ffma2(acc[2][2], xb.x, wp); ffma2(acc[2][3], xb.y, wp);
                    wp = pack2(w.w, w.w);
                    ffma2(acc[3][0], xa.x, wp); ffma2(acc[3][1], xa.y, wp);
                    ffma2(acc[3][2], xb.x, wp); ffma2(acc[3][3], xb.y, wp);
                }
            }
            mbar_arrive(bar0 + c_slot * 16 + 8);
            mbar_arrive_cluster(bar0 + c_slot * 16 + 8, peer);
            if (++c_slot == NCHUNK) { c_slot = 0; c_phase ^= 1; }
            if (tid == 300 && gi + NCHUNK < TOTAL) produce(gi + NCHUNK);
            ++gi;
        }
        __syncthreads();   // all reads of xh done before h is overwritten

        // =========== elementwise LSTM (registers) ===========
        if (m < HH) {
            #pragma unroll
            for (int p = 0; p < 4; ++p) {
                float2 iv = unpack2(acc[0][p]);
                float2 fv = unpack2(acc[1][p]);
                float2 gv = unpack2(acc[2][p]);
                float2 ov = unpack2(acc[3][p]);
                float cx = sigf(fv.x) * cst[2 * p]     + sigf(iv.x) * tanhf_fast(gv.x);
                float cy = sigf(fv.y) * cst[2 * p + 1] + sigf(iv.y) * tanhf_fast(gv.y);
                cst[2 * p]     = cx;
                cst[2 * p + 1] = cy;
                float hx = sigf(ov.x) * tanhf_fast(cx);
                float hy = sigf(ov.y) * tanhf_fast(cy);
                xh2[(HH + m) * 4 + p] = pack2(hx, hy);
            }
        }
        __syncthreads();   // h visible to all

        // =========== out GEMM ===========
        unsigned long long oacc[4];
        if (m < HH) {
            #pragma unroll
            for (int p = 0; p < 4; ++p) oacc[p] = pbo;
        }
        for (int tile = 0; tile < OT; ++tile) {
            int rows = (tile < OT - 1) ? 40 : 20;
            mbar_wait_acq(bar0 + c_slot * 16, (uint32_t)c_phase);
            const char* cbase = smem + SM_CHUNK + c_slot * CHUNK_BYTES;
            if (m < HH) {
                #pragma unroll 10
                for (int kl = 0; kl < rows; ++kl) {
                    int k = tile * 40 + kl;
                    ulonglong2 ha = xh4[(HH + k) * 2];
                    ulonglong2 hb = xh4[(HH + k) * 2 + 1];
                    float w = *(const float*)(cbase + kl * 1200 + m * 4);
                    unsigned long long wp = pack2(w, w);
                    ffma2(oacc[0], ha.x, wp); ffma2(oacc[1], ha.y, wp);
                    ffma2(oacc[2], hb.x, wp); ffma2(oacc[3], hb.y, wp);
                }
            }
            mbar_arrive(bar0 + c_slot * 16 + 8);
            mbar_arrive_cluster(bar0 + c_slot * 16 + 8, peer);
            if (++c_slot == NCHUNK) { c_slot = 0; c_phase ^= 1; }
            if (tid == 300 && gi + NCHUNK < TOTAL) produce(gi + NCHUNK);
            ++gi;
        }

        // write outputs + feed back x (disjoint from h region, no race)
        if (m < HH) {
            float* orow = out + ((size_t)t * B + r0) * HH;
            #pragma unroll
            for (int p = 0; p < 4; ++p) {
                float2 v = unpack2(oacc[p]);
                orow[(size_t)(2 * p) * HH + m]     = v.x;
                orow[(size_t)(2 * p + 1) * HH + m] = v.y;
                xh2[m * 4 + p] = oacc[p];
            }
        }
        __syncthreads();   // x visible before next gates GEMM
    }

    asm volatile("barrier.cluster.arrive.aligned;" ::: "memory");
    asm volatile("barrier.cluster.wait.aligned;" ::: "memory");
}

// ---------------- launch ----------------
extern "C" void kernel_launch(void* const* d_in, const int* in_sizes, int n_in,
                              void* d_out, int out_size) {
    const float* h0    = (const float*)d_in[0];
    const float* c0    = (const float*)d_in[1];
    const float* start = (const float*)d_in[2];
    const float* W_ih  = (const float*)d_in[3];
    const float* W_hh  = (const float*)d_in[4];
    const float* b_ih  = (const float*)d_in[5];
    const float* b_hh  = (const float*)d_in[6];
    const float* W_out = (const float*)d_in[7];
    const float* b_out = (const float*)d_in[8];

    int B = in_sizes[0] / HH;            // 1024
    int steps = out_size / (B * HH);     // 256

    int prep_elems = KK * G4 + HH * HH + G4;
    prep_kernel<<<(prep_elems + 255) / 256, 256>>>(W_ih, W_hh, b_ih, b_hh, W_out);

    cudaFuncSetAttribute(lstm_main, cudaFuncAttributeMaxDynamicSharedMemorySize,
                         SM_TOTAL);
    lstm_main<<<B / BCH, NT, SM_TOTAL>>>(h0, c0, start, b_out,
                                         (float*)d_out, B, steps);
}

// round 4
// speedup vs baseline: 2.2449x; 1.1431x over previous
#include <cuda_runtime.h>
#include <cstdint>

// Problem constants
#define HH   300
#define G4   1200          // 4*H
#define KK   600           // 2*H (x | h)
#define BCH  8             // batch rows per CTA
#define NT   640           // 608 compute + producer warp
#define CHUNK_BYTES 38400  // 8 gates k-rows (1200 f32) or 32 out k-rows (300 f32)
#define NCHUNK 5
#define GT 75              // gates tiles per step (600 k / 8)
#define OT 10              // out tiles per step (9x32 + 1x12 rows)
#define TPS (GT + OT)      // 85 tiles per step

// SMEM layout (bytes)
#define SM_XH    0                       // 600*8 floats = 19200 B
#define SM_BAR   19200                   // 5 slots x (full u64 + empty u64) = 80 B
#define SM_CHUNK 19280
#define SM_TOTAL (SM_CHUNK + NCHUNK*CHUNK_BYTES)   // 211280 B

// Persistent weights (allocation-free rule: __device__ globals)
__device__ __align__(256) float Wt2_g[KK * G4];    // [k][u*4+g] gate-interleaved
__device__ __align__(256) float WoutT_g[HH * HH];  // [k][n]
__device__ __align__(256) float bias2_g[G4];       // [u*4+g] fused b_ih+b_hh

// ---------------- packed f32x2 helpers ----------------
__device__ __forceinline__ unsigned long long pack2(float x, float y) {
    unsigned long long r;
    asm("mov.b64 %0, {%1, %2};" : "=l"(r) : "f"(x), "f"(y));
    return r;
}
__device__ __forceinline__ void ffma2(unsigned long long& d,
                                      unsigned long long a,
                                      unsigned long long b) {
    asm("fma.rn.f32x2 %0, %1, %2, %0;" : "+l"(d) : "l"(a), "l"(b));
}
__device__ __forceinline__ void fadd2(unsigned long long& d, unsigned long long a) {
    asm("add.rn.f32x2 %0, %0, %1;" : "+l"(d) : "l"(a));
}
__device__ __forceinline__ float2 unpack2(unsigned long long v) {
    float2 r;
    asm("mov.b64 {%0, %1}, %2;" : "=f"(r.x), "=f"(r.y) : "l"(v));
    return r;
}
__device__ __forceinline__ float sigf(float x) {
    return __fdividef(1.0f, 1.0f + __expf(-x));
}
__device__ __forceinline__ float tanhf_fast(float x) {
    return 1.0f - 2.0f * __fdividef(1.0f, __expf(2.0f * x) + 1.0f);
}

// ---------------- mbarrier / bulk-copy PTX ----------------
__device__ __forceinline__ uint32_t smem_u32(const void* p) {
    uint32_t a;
    asm("{ .reg .u64 t; cvta.to.shared.u64 t, %1; cvt.u32.u64 %0, t; }"
        : "=r"(a) : "l"(p));
    return a;
}
__device__ __forceinline__ uint32_t ctarank() {
    uint32_t r; asm("mov.u32 %0, %%cluster_ctarank;" : "=r"(r)); return r;
}
__device__ __forceinline__ void mbar_init(uint32_t a, uint32_t cnt) {
    asm volatile("mbarrier.init.shared.b64 [%0], %1;" :: "r"(a), "r"(cnt) : "memory");
}
__device__ __forceinline__ void mbar_expect_tx(uint32_t a, uint32_t bytes) {
    asm volatile("mbarrier.arrive.expect_tx.shared.b64 _, [%0], %1;"
                 :: "r"(a), "r"(bytes) : "memory");
}
__device__ __forceinline__ void mbar_arrive(uint32_t a) {
    asm volatile("mbarrier.arrive.shared.b64 _, [%0];" :: "r"(a) : "memory");
}
__device__ __forceinline__ void mbar_arrive_cluster(uint32_t a, uint32_t rankTgt) {
    asm volatile(
        "{\n\t.reg .b32 r;\n\t"
        "mapa.shared::cluster.u32 r, %0, %1;\n\t"
        "mbarrier.arrive.shared::cluster.b64 _, [r];\n\t}"
        :: "r"(a), "r"(rankTgt) : "memory");
}
__device__ __forceinline__ void mbar_wait_acq(uint32_t a, uint32_t parity) {
    asm volatile(
        "{\n\t.reg .pred P;\n"
        "LW_%=:\n\t"
        "mbarrier.try_wait.parity.acquire.cta.shared::cta.b64 P, [%0], %1, 0x989680;\n\t"
        "@P bra.uni LD_%=;\n\t"
        "bra.uni LW_%=;\n"
        "LD_%=:\n\t}"
        :: "r"(a), "r"(parity) : "memory");
}
__device__ __forceinline__ void mbar_wait_rlx(uint32_t a, uint32_t parity) {
    asm volatile(
        "{\n\t.reg .pred P;\n"
        "LW_%=:\n\t"
        "mbarrier.try_wait.parity.relaxed.cta.shared::cta.b64 P, [%0], %1, 0x989680;\n\t"
        "@P bra.uni LD_%=;\n\t"
        "bra.uni LW_%=;\n"
        "LD_%=:\n\t}"
        :: "r"(a), "r"(parity) : "memory");
}
__device__ __forceinline__ void bulk_mc(uint32_t dst, const void* src,
                                        uint32_t bytes, uint32_t mbar,
                                        uint16_t mask) {
    asm volatile(
        "cp.async.bulk.shared::cluster.global.mbarrier::complete_tx::bytes"
        ".multicast::cluster [%0], [%1], %2, [%3], %4;"
        :: "r"(dst), "l"(src), "r"(bytes), "r"(mbar), "h"(mask) : "memory");
}

// ---------------- prep: interleave/transpose weights, fuse biases ----------------
__global__ void prep_kernel(const float* __restrict__ W_ih,
                            const float* __restrict__ W_hh,
                            const float* __restrict__ b_ih,
                            const float* __restrict__ b_hh,
                            const float* __restrict__ W_out) {
    int idx = blockIdx.x * blockDim.x + threadIdx.x;
    if (idx < KK * G4) {
        int k = idx / G4;
        int col = idx % G4;            // u*4+g
        int u = col >> 2, g = col & 3;
        int n = u + HH * g;
        Wt2_g[idx] = (k < HH) ? W_ih[n * HH + k] : W_hh[n * HH + (k - HH)];
    }
    int i2 = idx - KK * G4;
    if (i2 >= 0 && i2 < HH * HH) {
        int k = i2 / HH, n = i2 % HH;
        WoutT_g[i2] = W_out[n * HH + k];
    }
    int i3 = idx - (KK * G4 + HH * HH);
    if (i3 >= 0 && i3 < G4) {
        int u = i3 >> 2, g = i3 & 3;
        bias2_g[i3] = b_ih[u + HH * g] + b_hh[u + HH * g];
    }
}

// ---------------- main persistent LSTM kernel ----------------
// Thread m (clamped mc) owns gate columns (2mc, 2mc+1) of the interleaved
// layout: even thread of a pair holds gates {i,f} of unit u=mc/2, odd holds
// {g,o}. Exchange via shfl.xor 1. Producer = thread 608 (warp 19).
__global__ void __launch_bounds__(NT, 1) __cluster_dims__(2, 1, 1)
lstm_main(const float* __restrict__ h0,
          const float* __restrict__ c0,
          const float* __restrict__ start,
          const float* __restrict__ b_out,
          float* __restrict__ out,
          int B, int steps) {
    extern __shared__ char smem[];
    float* xh = (float*)(smem + SM_XH);
    unsigned long long* xh2 = (unsigned long long*)xh;
    const ulonglong2* xh4 = (const ulonglong2*)xh;

    const uint32_t sbase = smem_u32(smem);
    const uint32_t bar0 = sbase + SM_BAR;
    const int tid = threadIdx.x;
    const int lane = tid & 31;
    const uint32_t rank = ctarank();
    const uint32_t peer = rank ^ 1u;
    const int r0 = blockIdx.x * BCH;
    const int TOTAL = steps * TPS;

    const bool comp = (tid < 608);           // warps 0..18 compute
    const bool act  = (tid < 600);           // threads allowed to store
    const int mc = act ? tid : (tid - 8);    // clamp keeps parity, stays in-bounds
    const int u  = mc >> 1;                  // hidden unit
    const int par = mc & 1;                  // 0: {i,f}, 1: {g,o}
    const bool evenT = (par == 0);

    // barriers: full[s] = bar0 + s*16 ; empty[s] = bar0 + s*16 + 8
    if (tid == 0) {
        #pragma unroll
        for (int s = 0; s < NCHUNK; ++s) {
            mbar_init(bar0 + s * 16, 1);       // full: expect_tx based
            mbar_init(bar0 + s * 16 + 8, 38);  // empty: 19 warps x 2 CTAs
        }
    }
    __syncthreads();
    asm volatile("barrier.cluster.arrive.aligned;" ::: "memory");
    asm volatile("barrier.cluster.wait.aligned;" ::: "memory");

    // initial state: x = start, h = h0 into xh
    for (int idx = tid; idx < HH * BCH; idx += NT) {
        int k = idx >> 3, b = idx & 7;
        xh[k * BCH + b]        = start[(size_t)(r0 + b) * HH + k];
        xh[(HH + k) * BCH + b] = h0[(size_t)(r0 + b) * HH + k];
    }
    // per-thread constants
    float cst[BCH];
    unsigned long long pb[2], pbo = pack2(0.0f, 0.0f);
    if (comp) {
        float2 bb = *(const float2*)&bias2_g[mc * 2];
        pb[0] = pack2(bb.x, bb.x);
        pb[1] = pack2(bb.y, bb.y);
        if (evenT) {
            // BUGFIX (R3): only the even thread of a pair seeds the output
            // bias; the pair-reduction (fadd2 of both halves) would otherwise
            // count b_out twice.
            float bo = __ldg(&b_out[u]);
            pbo = pack2(bo, bo);
            #pragma unroll
            for (int b = 0; b < BCH; ++b) cst[b] = c0[(size_t)(r0 + b) * HH + u];
        }
    }
    __syncthreads();

    // producer cursor (thread 608 only)
    int p_slot = 0, p_phase = 1;
    auto produce = [&](int g) {
        mbar_wait_rlx(bar0 + p_slot * 16 + 8, (uint32_t)p_phase);  // wait empty
        int j = g % TPS;
        const char* src; int bytes;
        if (j < GT) {
            src = (const char*)Wt2_g + (size_t)j * CHUNK_BYTES;
            bytes = CHUNK_BYTES;
        } else {
            int jj = j - GT;
            src = (const char*)WoutT_g + (size_t)jj * CHUNK_BYTES;
            bytes = (jj < OT - 1) ? CHUNK_BYTES : 14400;
        }
        int half = bytes >> 1;
        uint32_t full = bar0 + p_slot * 16;
        uint32_t dst = sbase + SM_CHUNK + p_slot * CHUNK_BYTES + rank * half;
        mbar_expect_tx(full, (uint32_t)bytes);     // expect FULL tile locally
        bulk_mc(dst, src + (size_t)rank * half, (uint32_t)half, full, 0x3);
        if (++p_slot == NCHUNK) { p_slot = 0; p_phase ^= 1; }
    };

    if (tid == 608) {
        #pragma unroll
        for (int i = 0; i < NCHUNK; ++i) produce(i);
    }

    int c_slot = 0, c_phase = 0, gi = 0;

    for (int t = 0; t < steps; ++t) {
        // =========== gates GEMM: acc[2 gates][4 batch pairs] ===========
        unsigned long long acc[2][4];
        #pragma unroll
        for (int g = 0; g < 2; ++g)
            #pragma unroll
            for (int p = 0; p < 4; ++p) acc[g][p] = pb[g];

        for (int tile = 0; tile < GT; ++tile) {
            if (comp) {
                mbar_wait_acq(bar0 + c_slot * 16, (uint32_t)c_phase);
                const char* cb = smem + SM_CHUNK + c_slot * CHUNK_BYTES;
                #pragma unroll
                for (int kl = 0; kl < 8; ++kl) {
                    int k = tile * 8 + kl;
                    ulonglong2 xa = xh4[k * 2];
                    ulonglong2 xb = xh4[k * 2 + 1];
                    float2 w = *(const float2*)(cb + kl * 4800 + mc * 8);
                    unsigned long long w0 = pack2(w.x, w.x);
                    unsigned long long w1 = pack2(w.y, w.y);
                    ffma2(acc[0][0], xa.x, w0); ffma2(acc[0][1], xa.y, w0);
                    ffma2(acc[0][2], xb.x, w0); ffma2(acc[0][3], xb.y, w0);
                    ffma2(acc[1][0], xa.x, w1); ffma2(acc[1][1], xa.y, w1);
                    ffma2(acc[1][2], xb.x, w1); ffma2(acc[1][3], xb.y, w1);
                }
                if (lane == 0) {
                    mbar_arrive(bar0 + c_slot * 16 + 8);
                    mbar_arrive_cluster(bar0 + c_slot * 16 + 8, peer);
                }
            }
            if (tid == 608 && gi + NCHUNK < TOTAL) produce(gi + NCHUNK);
            if (++c_slot == NCHUNK) { c_slot = 0; c_phase ^= 1; }
            ++gi;
        }
        __syncthreads();   // all gates reads of xh done before h overwrite

        // =========== elementwise LSTM (shuffle exchange within pair) ===========
        if (comp) {
            unsigned long long rg[2][4];
            #pragma unroll
            for (int g = 0; g < 2; ++g)
                #pragma unroll
                for (int p = 0; p < 4; ++p)
                    rg[g][p] = __shfl_xor_sync(0xffffffffu, acc[g][p], 1);
            if (evenT) {   // even: acc={i,f}, rg={g,o}
                #pragma unroll
                for (int p = 0; p < 4; ++p) {
                    float2 iv = unpack2(acc[0][p]);
                    float2 fv = unpack2(acc[1][p]);
                    float2 gv = unpack2(rg[0][p]);
                    float2 ov = unpack2(rg[1][p]);
                    float cx = sigf(fv.x) * cst[2*p]   + sigf(iv.x) * tanhf_fast(gv.x);
                    float cy = sigf(fv.y) * cst[2*p+1] + sigf(iv.y) * tanhf_fast(gv.y);
                    cst[2*p] = cx; cst[2*p+1] = cy;
                    float hx = sigf(ov.x) * tanhf_fast(cx);
                    float hy = sigf(ov.y) * tanhf_fast(cy);
                    if (act) xh2[(HH + u) * 4 + p] = pack2(hx, hy);
                }
            }
        }
        __syncthreads();   // h visible to all

        // =========== out GEMM: pair splits k by row parity ===========
        unsigned long long oacc[4];
        #pragma unroll
        for (int p = 0; p < 4; ++p) oacc[p] = pbo;   // bias only on even thread

        for (int tile = 0; tile < OT; ++tile) {
            int half = (tile < OT - 1) ? 16 : 6;
            if (comp) {
                mbar_wait_acq(bar0 + c_slot * 16, (uint32_t)c_phase);
                const char* cb = smem + SM_CHUNK + c_slot * CHUNK_BYTES;
                #pragma unroll 8
                for (int r = 0; r < half; ++r) {
                    int kl = 2 * r + par;
                    int k = tile * 32 + kl;
                    ulonglong2 ha = xh4[(HH + k) * 2];
                    ulonglong2 hb = xh4[(HH + k) * 2 + 1];
                    float w = *(const float*)(cb + kl * 1200 + u * 4);
                    unsigned long long wp = pack2(w, w);
                    ffma2(oacc[0], ha.x, wp); ffma2(oacc[1], ha.y, wp);
                    ffma2(oacc[2], hb.x, wp); ffma2(oacc[3], hb.y, wp);
                }
                if (lane == 0) {
                    mbar_arrive(bar0 + c_slot * 16 + 8);
                    mbar_arrive_cluster(bar0 + c_slot * 16 + 8, peer);
                }
            }
            if (tid == 608 && gi + NCHUNK < TOTAL) produce(gi + NCHUNK);
            if (++c_slot == NCHUNK) { c_slot = 0; c_phase ^= 1; }
            ++gi;
        }

        // reduce pair partials, write outputs + feed back x
        if (comp) {
            #pragma unroll
            for (int p = 0; p < 4; ++p) {
                unsigned long long o = __shfl_xor_sync(0xffffffffu, oacc[p], 1);
                fadd2(oacc[p], o);
            }
            if (evenT && act) {
                float* orow = out + ((size_t)t * B + r0) * HH;
                #pragma unroll
                for (int p = 0; p < 4; ++p) {
                    float2 v = unpack2(oacc[p]);
                    orow[(size_t)(2 * p) * HH + u]     = v.x;
                    orow[(size_t)(2 * p + 1) * HH + u] = v.y;
                    xh2[u * 4 + p] = oacc[p];
                }
            }
        }
        __syncthreads();   // x visible before next gates GEMM
    }

    asm volatile("barrier.cluster.arrive.aligned;" ::: "memory");
    asm volatile("barrier.cluster.wait.aligned;" ::: "memory");
}

// ---------------- launch ----------------
extern "C" void kernel_launch(void* const* d_in, const int* in_sizes, int n_in,
                              void* d_out, int out_size) {
    const float* h0    = (const float*)d_in[0];
    const float* c0    = (const float*)d_in[1];
    const float* start = (const float*)d_in[2];
    const float* W_ih  = (const float*)d_in[3];
    const float* W_hh  = (const float*)d_in[4];
    const float* b_ih  = (const float*)d_in[5];
    const float* b_hh  = (const float*)d_in[6];
    const float* W_out = (const float*)d_in[7];
    const float* b_out = (const float*)d_in[8];

    int B = in_sizes[0] / HH;            // 1024
    int steps = out_size / (B * HH);     // 256

    int prep_elems = KK * G4 + HH * HH + G4;
    prep_kernel<<<(prep_elems + 255) / 256, 256>>>(W_ih, W_hh, b_ih, b_hh, W_out);

    cudaFuncSetAttribute(lstm_main, cudaFuncAttributeMaxDynamicSharedMemorySize,
                         SM_TOTAL);
    lstm_main<<<B / BCH, NT, SM_TOTAL>>>(h0, c0, start, b_out,
                                         (float*)d_out, B, steps);
}

// round 5
// speedup vs baseline: 3.8652x; 1.7218x over previous
#include <cuda_runtime.h>
#include <cstdint>

// Problem constants
#define HH   300
#define G4   1200          // 4*H
#define KK   600           // 2*H (x | h), step-0 only
#define BCH  8             // batch rows per CTA
#define NT   640           // 608 compute + producer warp
#define CHUNK_BYTES 48000  // 10 gate k-rows (1200 f32) or 40 out k-rows (300 f32)
#define NCHUNK 4
#define GT0 60             // step-0 gates tiles (600 k / 10)
#define GTF 30             // folded gates tiles (300 k / 10)
#define OT  8              // out tiles (7x40 + 1x20 rows)
#define TPS0 (GT0 + OT)    // 68
#define TPSF (GTF + OT)    // 38

// SMEM layout (bytes)
#define SM_XH    0                       // 600*8 floats = 19200 B
#define SM_BAR   19200                   // 4 slots x (full u64 + empty u64)
#define SM_CHUNK 19264
#define SM_TOTAL (SM_CHUNK + NCHUNK*CHUNK_BYTES)   // 211264 B

// Persistent weights (allocation-free rule: __device__ globals)
__device__ __align__(256) float Wt2_g[KK * G4];    // step-0: [k][u*4+g], 2.88 MB
__device__ __align__(256) float Wc2_g[HH * G4];    // folded: [k][u*4+g], 1.44 MB
__device__ __align__(256) float WoutT_g[HH * HH];  // [k][n], 360 KB
__device__ __align__(256) float bias2_g[G4];       // step-0 bias  (b_ih+b_hh)
__device__ __align__(256) float biasf_g[G4];       // folded bias  (+ W_ih b_out)

// ---------------- packed f32x2 helpers ----------------
__device__ __forceinline__ unsigned long long pack2(float x, float y) {
    unsigned long long r;
    asm("mov.b64 %0, {%1, %2};" : "=l"(r) : "f"(x), "f"(y));
    return r;
}
__device__ __forceinline__ void ffma2(unsigned long long& d,
                                      unsigned long long a,
                                      unsigned long long b) {
    asm("fma.rn.f32x2 %0, %1, %2, %0;" : "+l"(d) : "l"(a), "l"(b));
}
__device__ __forceinline__ void fadd2(unsigned long long& d, unsigned long long a) {
    asm("add.rn.f32x2 %0, %0, %1;" : "+l"(d) : "l"(a));
}
__device__ __forceinline__ float2 unpack2(unsigned long long v) {
    float2 r;
    asm("mov.b64 {%0, %1}, %2;" : "=f"(r.x), "=f"(r.y) : "l"(v));
    return r;
}
__device__ __forceinline__ float sigf(float x) {
    return __fdividef(1.0f, 1.0f + __expf(-x));
}
__device__ __forceinline__ float tanhf_fast(float x) {
    return 1.0f - 2.0f * __fdividef(1.0f, __expf(2.0f * x) + 1.0f);
}

// ---------------- mbarrier / bulk-copy PTX ----------------
__device__ __forceinline__ uint32_t smem_u32(const void* p) {
    uint32_t a;
    asm("{ .reg .u64 t; cvta.to.shared.u64 t, %1; cvt.u32.u64 %0, t; }"
        : "=r"(a) : "l"(p));
    return a;
}
__device__ __forceinline__ uint32_t ctarank() {
    uint32_t r; asm("mov.u32 %0, %%cluster_ctarank;" : "=r"(r)); return r;
}
__device__ __forceinline__ void mbar_init(uint32_t a, uint32_t cnt) {
    asm volatile("mbarrier.init.shared.b64 [%0], %1;" :: "r"(a), "r"(cnt) : "memory");
}
__device__ __forceinline__ void mbar_expect_tx(uint32_t a, uint32_t bytes) {
    asm volatile("mbarrier.arrive.expect_tx.shared.b64 _, [%0], %1;"
                 :: "r"(a), "r"(bytes) : "memory");
}
__device__ __forceinline__ void mbar_arrive(uint32_t a) {
    asm volatile("mbarrier.arrive.shared.b64 _, [%0];" :: "r"(a) : "memory");
}
__device__ __forceinline__ void mbar_arrive_cluster(uint32_t a, uint32_t rankTgt) {
    asm volatile(
        "{\n\t.reg .b32 r;\n\t"
        "mapa.shared::cluster.u32 r, %0, %1;\n\t"
        "mbarrier.arrive.shared::cluster.b64 _, [r];\n\t}"
        :: "r"(a), "r"(rankTgt) : "memory");
}
__device__ __forceinline__ void mbar_wait_acq(uint32_t a, uint32_t parity) {
    asm volatile(
        "{\n\t.reg .pred P;\n"
        "LW_%=:\n\t"
        "mbarrier.try_wait.parity.acquire.cta.shared::cta.b64 P, [%0], %1, 0x989680;\n\t"
        "@P bra.uni LD_%=;\n\t"
        "bra.uni LW_%=;\n"
        "LD_%=:\n\t}"
        :: "r"(a), "r"(parity) : "memory");
}
__device__ __forceinline__ void mbar_wait_rlx(uint32_t a, uint32_t parity) {
    asm volatile(
        "{\n\t.reg .pred P;\n"
        "LW_%=:\n\t"
        "mbarrier.try_wait.parity.relaxed.cta.shared::cta.b64 P, [%0], %1, 0x989680;\n\t"
        "@P bra.uni LD_%=;\n\t"
        "bra.uni LW_%=;\n"
        "LD_%=:\n\t}"
        :: "r"(a), "r"(parity) : "memory");
}
__device__ __forceinline__ void bulk_mc(uint32_t dst, const void* src,
                                        uint32_t bytes, uint32_t mbar,
                                        uint16_t mask) {
    asm volatile(
        "cp.async.bulk.shared::cluster.global.mbarrier::complete_tx::bytes"
        ".multicast::cluster [%0], [%1], %2, [%3], %4;"
        :: "r"(dst), "l"(src), "r"(bytes), "r"(mbar), "h"(mask) : "memory");
}

// ---------------- prep 1: transpose/interleave raw weights ----------------
__global__ void prep_basic(const float* __restrict__ W_ih,
                           const float* __restrict__ W_hh,
                           const float* __restrict__ b_ih,
                           const float* __restrict__ b_hh,
                           const float* __restrict__ W_out) {
    int idx = blockIdx.x * blockDim.x + threadIdx.x;
    if (idx < KK * G4) {
        int k = idx / G4;
        int col = idx % G4;            // u*4+g
        int u = col >> 2, g = col & 3;
        int n = u + HH * g;
        Wt2_g[idx] = (k < HH) ? W_ih[n * HH + k] : W_hh[n * HH + (k - HH)];
    }
    int i2 = idx - KK * G4;
    if (i2 >= 0 && i2 < HH * HH) {
        int k = i2 / HH, n = i2 % HH;
        WoutT_g[i2] = W_out[n * HH + k];
    }
    int i3 = idx - (KK * G4 + HH * HH);
    if (i3 >= 0 && i3 < G4) {
        int u = i3 >> 2, g = i3 & 3;
        bias2_g[i3] = b_ih[u + HH * g] + b_hh[u + HH * g];
    }
}

// ---------------- prep 2: folded weights Wc = W_ih*W_out + W_hh ----------------
// grid: (75 col-tiles of 16, 15 k-tiles of 20), block 320 = 16 cols x 20 k
__global__ void prep_fold(const float* __restrict__ W_ih,
                          const float* __restrict__ W_hh,
                          const float* __restrict__ W_out) {
    __shared__ float s_wout[HH][20];   // W_out[j][k-tile]
    int tid = threadIdx.x;
    int kk = tid % 20;
    int c  = tid / 20;                 // 0..15
    int k  = blockIdx.y * 20 + kk;
    int col = blockIdx.x * 16 + c;     // interleaved col
    int u = col >> 2, g = col & 3;
    int n = u + HH * g;

    for (int idx = tid; idx < HH * 20; idx += 320) {
        int j = idx / 20, kl = idx % 20;
        s_wout[j][kl] = W_out[j * HH + blockIdx.y * 20 + kl];
    }
    __syncthreads();

    float acc = W_hh[n * HH + k];
    const float* wr = &W_ih[n * HH];
    #pragma unroll 4
    for (int j = 0; j < HH; ++j)
        acc = fmaf(__ldg(&wr[j]), s_wout[j][kk], acc);
    Wc2_g[k * G4 + col] = acc;
}

// ---------------- prep 3: folded bias = bias2 + W_ih * b_out ----------------
__global__ void prep_biasf(const float* __restrict__ W_ih,
                           const float* __restrict__ b_ih,
                           const float* __restrict__ b_hh,
                           const float* __restrict__ b_out) {
    int col = blockIdx.x * blockDim.x + threadIdx.x;
    if (col >= G4) return;
    int u = col >> 2, g = col & 3;
    int n = u + HH * g;
    float acc = b_ih[n] + b_hh[n];
    const float* wr = &W_ih[n * HH];
    #pragma unroll 4
    for (int j = 0; j < HH; ++j)
        acc = fmaf(__ldg(&wr[j]), __ldg(&b_out[j]), acc);
    biasf_g[col] = acc;
}

// ---------------- main persistent LSTM kernel ----------------
// Thread pair owns gate columns (2mc, 2mc+1); even thread holds {i,f} of unit
// u=mc/2, odd holds {g,o}; exchange via shfl.xor 1. Producer = thread 608.
// Step 0 uses K=600 raw weights (x0=start | h0); steps>=1 use folded K=300.
__global__ void __launch_bounds__(NT, 1) __cluster_dims__(2, 1, 1)
lstm_main(const float* __restrict__ h0,
          const float* __restrict__ c0,
          const float* __restrict__ start,
          const float* __restrict__ b_out,
          float* __restrict__ out,
          int B, int steps) {
    extern __shared__ char smem[];
    float* xh = (float*)(smem + SM_XH);
    unsigned long long* xh2 = (unsigned long long*)xh;
    const ulonglong2* xh4 = (const ulonglong2*)xh;

    const uint32_t sbase = smem_u32(smem);
    const uint32_t bar0 = sbase + SM_BAR;
    const int tid = threadIdx.x;
    const int lane = tid & 31;
    const uint32_t rank = ctarank();
    const uint32_t peer = rank ^ 1u;
    const int r0 = blockIdx.x * BCH;
    const int TOTAL = TPS0 + (steps - 1) * TPSF;

    const bool comp = (tid < 608);           // warps 0..18 compute
    const bool act  = (tid < 600);
    const int mc = act ? tid : (tid - 8);    // clamp keeps parity, in-bounds
    const int u  = mc >> 1;
    const int par = mc & 1;                  // 0: {i,f}, 1: {g,o}
    const bool evenT = (par == 0);

    if (tid == 0) {
        #pragma unroll
        for (int s = 0; s < NCHUNK; ++s) {
            mbar_init(bar0 + s * 16, 1);       // full: expect_tx based
            mbar_init(bar0 + s * 16 + 8, 38);  // empty: 19 warps x 2 CTAs
        }
    }
    __syncthreads();
    asm volatile("barrier.cluster.arrive.aligned;" ::: "memory");
    asm volatile("barrier.cluster.wait.aligned;" ::: "memory");

    // initial state: x = start (rows 0..299), h = h0 (rows 300..599)
    for (int idx = tid; idx < HH * BCH; idx += NT) {
        int k = idx >> 3, b = idx & 7;
        xh[k * BCH + b]        = start[(size_t)(r0 + b) * HH + k];
        xh[(HH + k) * BCH + b] = h0[(size_t)(r0 + b) * HH + k];
    }
    float cst[BCH];
    unsigned long long pb0[2], pbf[2], pbo = pack2(0.0f, 0.0f);
    if (comp) {
        float2 b0 = *(const float2*)&bias2_g[mc * 2];
        float2 bf = *(const float2*)&biasf_g[mc * 2];
        pb0[0] = pack2(b0.x, b0.x); pb0[1] = pack2(b0.y, b0.y);
        pbf[0] = pack2(bf.x, bf.x); pbf[1] = pack2(bf.y, bf.y);
        if (evenT) {
            float bo = __ldg(&b_out[u]);
            pbo = pack2(bo, bo);                // bias only on even thread of pair
            #pragma unroll
            for (int b = 0; b < BCH; ++b) cst[b] = c0[(size_t)(r0 + b) * HH + u];
        }
    }
    __syncthreads();

    // producer cursor (thread 608 only)
    int p_slot = 0, p_phase = 1;
    auto produce = [&](int g) {
        mbar_wait_rlx(bar0 + p_slot * 16 + 8, (uint32_t)p_phase);  // wait empty
        const char* src; int bytes = CHUNK_BYTES;
        if (g < GT0) {
            src = (const char*)Wt2_g + (size_t)g * CHUNK_BYTES;
        } else if (g < TPS0) {
            int jj = g - GT0;
            src = (const char*)WoutT_g + (size_t)jj * CHUNK_BYTES;
            if (jj == OT - 1) bytes = 24000;
        } else {
            int r = (g - TPS0) % TPSF;
            if (r < GTF) {
                src = (const char*)Wc2_g + (size_t)r * CHUNK_BYTES;
            } else {
                int jj = r - GTF;
                src = (const char*)WoutT_g + (size_t)jj * CHUNK_BYTES;
                if (jj == OT - 1) bytes = 24000;
            }
        }
        int half = bytes >> 1;
        uint32_t full = bar0 + p_slot * 16;
        uint32_t dst = sbase + SM_CHUNK + p_slot * CHUNK_BYTES + rank * half;
        mbar_expect_tx(full, (uint32_t)bytes);     // expect FULL tile locally
        bulk_mc(dst, src + (size_t)rank * half, (uint32_t)half, full, 0x3);
        if (++p_slot == NCHUNK) { p_slot = 0; p_phase ^= 1; }
    };

    if (tid == 608) {
        #pragma unroll
        for (int i = 0; i < NCHUNK; ++i) produce(i);
    }

    int c_slot = 0, c_phase = 0, gi = 0;

    for (int t = 0; t < steps; ++t) {
        const int ngt   = (t == 0) ? GT0 : GTF;
        const int kbase = (t == 0) ? 0 : HH;   // step0 reads x|h, later only h

        // =========== gates GEMM: acc[2 gates][4 batch pairs] ===========
        unsigned long long acc[2][4];
        #pragma unroll
        for (int g = 0; g < 2; ++g) {
            unsigned long long b = (t == 0) ? pb0[g] : pbf[g];
            #pragma unroll
            for (int p = 0; p < 4; ++p) acc[g][p] = b;
        }

        for (int tile = 0; tile < ngt; ++tile) {
            if (comp) {
                mbar_wait_acq(bar0 + c_slot * 16, (uint32_t)c_phase);
                const char* cb = smem + SM_CHUNK + c_slot * CHUNK_BYTES;
                #pragma unroll
                for (int kl = 0; kl < 10; ++kl) {
                    int xi = kbase + tile * 10 + kl;
                    ulonglong2 xa = xh4[xi * 2];
                    ulonglong2 xb = xh4[xi * 2 + 1];
                    float2 w = *(const float2*)(cb + kl * 4800 + mc * 8);
                    unsigned long long w0 = pack2(w.x, w.x);
                    unsigned long long w1 = pack2(w.y, w.y);
                    ffma2(acc[0][0], xa.x, w0); ffma2(acc[0][1], xa.y, w0);
                    ffma2(acc[0][2], xb.x, w0); ffma2(acc[0][3], xb.y, w0);
                    ffma2(acc[1][0], xa.x, w1); ffma2(acc[1][1], xa.y, w1);
                    ffma2(acc[1][2], xb.x, w1); ffma2(acc[1][3], xb.y, w1);
                }
                if (lane == 0) {
                    mbar_arrive(bar0 + c_slot * 16 + 8);
                    mbar_arrive_cluster(bar0 + c_slot * 16 + 8, peer);
                }
            }
            if (tid == 608 && gi + NCHUNK < TOTAL) produce(gi + NCHUNK);
            if (++c_slot == NCHUNK) { c_slot = 0; c_phase ^= 1; }
            ++gi;
        }
        __syncthreads();   // gates reads of h done before h overwrite

        // =========== elementwise LSTM (shuffle exchange within pair) ===========
        if (comp) {
            unsigned long long rg[2][4];
            #pragma unroll
            for (int g = 0; g < 2; ++g)
                #pragma unroll
                for (int p = 0; p < 4; ++p)
                    rg[g][p] = __shfl_xor_sync(0xffffffffu, acc[g][p], 1);
            if (evenT) {   // even: acc={i,f}, rg={g,o}
                #pragma unroll
                for (int p = 0; p < 4; ++p) {
                    float2 iv = unpack2(acc[0][p]);
                    float2 fv = unpack2(acc[1][p]);
                    float2 gv = unpack2(rg[0][p]);
                    float2 ov = unpack2(rg[1][p]);
                    float cx = sigf(fv.x) * cst[2*p]   + sigf(iv.x) * tanhf_fast(gv.x);
                    float cy = sigf(fv.y) * cst[2*p+1] + sigf(iv.y) * tanhf_fast(gv.y);
                    cst[2*p] = cx; cst[2*p+1] = cy;
                    float hx = sigf(ov.x) * tanhf_fast(cx);
                    float hy = sigf(ov.y) * tanhf_fast(cy);
                    if (act) xh2[(HH + u) * 4 + p] = pack2(hx, hy);
                }
            }
        }
        __syncthreads();   // new h visible to all

        // =========== out GEMM: pair splits k by row parity ===========
        unsigned long long oacc[4];
        #pragma unroll
        for (int p = 0; p < 4; ++p) oacc[p] = pbo;

        for (int tile = 0; tile < OT; ++tile) {
            int half = (tile < OT - 1) ? 20 : 10;    // 40-row tiles, last 20
            if (comp) {
                mbar_wait_acq(bar0 + c_slot * 16, (uint32_t)c_phase);
                const char* cb = smem + SM_CHUNK + c_slot * CHUNK_BYTES;
                #pragma unroll 10
                for (int r = 0; r < half; ++r) {
                    int kl = 2 * r + par;
                    int k = tile * 40 + kl;
                    ulonglong2 ha = xh4[(HH + k) * 2];
                    ulonglong2 hb = xh4[(HH + k) * 2 + 1];
                    float w = *(const float*)(cb + kl * 1200 + u * 4);
                    unsigned long long wp = pack2(w, w);
                    ffma2(oacc[0], ha.x, wp); ffma2(oacc[1], ha.y, wp);
                    ffma2(oacc[2], hb.x, wp); ffma2(oacc[3], hb.y, wp);
                }
                if (lane == 0) {
                    mbar_arrive(bar0 + c_slot * 16 + 8);
                    mbar_arrive_cluster(bar0 + c_slot * 16 + 8, peer);
                }
            }
            if (tid == 608 && gi + NCHUNK < TOTAL) produce(gi + NCHUNK);
            if (++c_slot == NCHUNK) { c_slot = 0; c_phase ^= 1; }
            ++gi;
        }

        // reduce pair partials, write outputs (no x feedback needed: folded)
        if (comp) {
            #pragma unroll
            for (int p = 0; p < 4; ++p) {
                unsigned long long o = __shfl_xor_sync(0xffffffffu, oacc[p], 1);
                fadd2(oacc[p], o);
            }
            if (evenT && act) {
                float* orow = out + ((size_t)t * B + r0) * HH;
                #pragma unroll
                for (int p = 0; p < 4; ++p) {
                    float2 v = unpack2(oacc[p]);
                    orow[(size_t)(2 * p) * HH + u]     = v.x;
                    orow[(size_t)(2 * p + 1) * HH + u] = v.y;
                }
            }
        }
        __syncthreads();   // h stable before next gates GEMM
    }

    asm volatile("barrier.cluster.arrive.aligned;" ::: "memory");
    asm volatile("barrier.cluster.wait.aligned;" ::: "memory");
}

// ---------------- launch ----------------
extern "C" void kernel_launch(void* const* d_in, const int* in_sizes, int n_in,
                              void* d_out, int out_size) {
    const float* h0    = (const float*)d_in[0];
    const float* c0    = (const float*)d_in[1];
    const float* start = (const float*)d_in[2];
    const float* W_ih  = (const float*)d_in[3];
    const float* W_hh  = (const float*)d_in[4];
    const float* b_ih  = (const float*)d_in[5];
    const float* b_hh  = (const float*)d_in[6];
    const float* W_out = (const float*)d_in[7];
    const float* b_out = (const float*)d_in[8];

    int B = in_sizes[0] / HH;            // 1024
    int steps = out_size / (B * HH);     // 256

    int prep_elems = KK * G4 + HH * HH + G4;
    prep_basic<<<(prep_elems + 255) / 256, 256>>>(W_ih, W_hh, b_ih, b_hh, W_out);

    dim3 fg(G4 / 16, HH / 20);           // 75 x 15
    prep_fold<<<fg, 320>>>(W_ih, W_hh, W_out);
    prep_biasf<<<(G4 + 255) / 256, 256>>>(W_ih, b_ih, b_hh, b_out);

    cudaFuncSetAttribute(lstm_main, cudaFuncAttributeMaxDynamicSharedMemorySize,
                         SM_TOTAL);
    lstm_main<<<B / BCH, NT, SM_TOTAL>>>(h0, c0, start, b_out,
                                         (float*)d_out, B, steps);
}